// round 5
// baseline (speedup 1.0000x reference)
#include <cuda_runtime.h>
#include <cuda_bf16.h>
#include <cstdint>

#define Bsz 8
#define Nn 2048
#define SSTR 2052
#define CAP 1024
#define TK 128

// ---------------- fused kernel smem layout (bytes) ----------------
#define OFF_S    0                   // 16 x 2052 fp32 strip = 131,328
#define OFF_K0   131328              // 2 groups x (KH 128x144 + KL 128x144)
#define KBUF_SZ  36864
#define KHALF    18432
#define OFF_QH   205056
#define OFF_QL   207360              // each Q split 16x144 = 2,304
#define OFF_STAT 209664
// stats: sM 64 | sL 64 | sCnt 64 | sLp 128 | sMp 2048 | sPV 4096
#define SMEM_TOTAL 216128

__device__ float          g_V [Bsz * Nn * 64];
__device__ __nv_bfloat16  g_Qh[Bsz * Nn * 64];
__device__ __nv_bfloat16  g_Ql[Bsz * Nn * 64];
__device__ __nv_bfloat16  g_Kh[Bsz * Nn * 64];
__device__ __nv_bfloat16  g_Kl[Bsz * Nn * 64];

// ================= helpers =================
__device__ __forceinline__ uint32_t smem_u32(const void* p) {
    uint32_t a;
    asm("{ .reg .u64 t; cvta.to.shared.u64 t, %1; cvt.u32.u64 %0, t; }" : "=r"(a) : "l"(p));
    return a;
}
__device__ __forceinline__ void cp16(uint32_t dst, const void* src) {
    asm volatile("cp.async.cg.shared.global [%0], [%1], 16;" :: "r"(dst), "l"(src));
}
#define CP_COMMIT()  asm volatile("cp.async.commit_group;" ::: "memory")
#define CP_WAIT(n)   asm volatile("cp.async.wait_group %0;" :: "n"(n) : "memory")
#define GBAR(id)     asm volatile("bar.sync %0, 512;" :: "r"(id) : "memory")

#define LDSM_X4(r0, r1, r2, r3, addr)                                          \
    asm volatile("ldmatrix.sync.aligned.m8n8.x4.shared.b16 {%0,%1,%2,%3}, [%4];" \
        : "=r"(r0), "=r"(r1), "=r"(r2), "=r"(r3) : "r"(addr))

__device__ __forceinline__ void mma16816(float* d, const uint32_t* a, const uint32_t* b) {
    asm volatile(
        "mma.sync.aligned.m16n8k16.row.col.f32.bf16.bf16.f32 "
        "{%0,%1,%2,%3}, {%4,%5,%6,%7}, {%8,%9}, {%0,%1,%2,%3};"
        : "+f"(d[0]), "+f"(d[1]), "+f"(d[2]), "+f"(d[3])
        : "r"(a[0]), "r"(a[1]), "r"(a[2]), "r"(a[3]), "r"(b[0]), "r"(b[1]));
}

// ---------------------------------------------------------------------------
// Kernel A: QKV projection -> bf16 hi/lo Q,K splits + fp32 V.
// ---------------------------------------------------------------------------
__global__ __launch_bounds__(256) void qkv_kernel(
    const float* __restrict__ x,
    const float* __restrict__ Wq, const float* __restrict__ bq,
    const float* __restrict__ Wk, const float* __restrict__ bk,
    const float* __restrict__ Wv, const float* __restrict__ bv)
{
    __shared__ float sX[64 * 68];
    int tid = threadIdx.x;
    size_t base = (size_t)blockIdx.x * 64;

#pragma unroll
    for (int i = 0; i < 4; i++) {
        int slot = i * 256 + tid;
        int row  = slot >> 4;
        int d4   = (slot & 15) << 2;
        float4 v = *(const float4*)(x + (base + row) * 64 + d4);
        *(float4*)(sX + row * 68 + d4) = v;
    }
    __syncthreads();

    int c  = tid & 63;
    int rg = tid >> 6;

#pragma unroll 1
    for (int m = 0; m < 3; m++) {
        const float* W  = (m == 0) ? Wq : (m == 1) ? Wk : Wv;
        const float* bb = (m == 0) ? bq : (m == 1) ? bk : bv;
        float wcol[64];
#pragma unroll
        for (int d = 0; d < 64; d++) wcol[d] = W[d * 64 + c];
        float bias = bb[c];

#pragma unroll 1
        for (int rr = 0; rr < 16; rr++) {
            int r = rg * 16 + rr;
            const float* xr = sX + r * 68;
            float a0 = 0.f, a1 = 0.f, a2 = 0.f, a3 = 0.f;
#pragma unroll
            for (int d = 0; d < 64; d += 4) {
                float4 xv = *(const float4*)(xr + d);
                a0 += xv.x * wcol[d];
                a1 += xv.y * wcol[d + 1];
                a2 += xv.z * wcol[d + 2];
                a3 += xv.w * wcol[d + 3];
            }
            float acc = ((a0 + a1) + (a2 + a3)) + bias;
            size_t idx = (base + r) * 64 + c;
            if (m == 2) {
                g_V[idx] = acc;
            } else {
                __nv_bfloat16 hi = __float2bfloat16(acc);
                __nv_bfloat16 lo = __float2bfloat16(acc - __bfloat162float(hi));
                if (m == 0) { g_Qh[idx] = hi; g_Ql[idx] = lo; }
                else        { g_Kh[idx] = hi; g_Kl[idx] = lo; }
            }
        }
    }
}

// ---------------------------------------------------------------------------
// Kernel B (fused): 1024 threads = 2 warp-groups of 16 in chunk ping-pong.
// HMMA scores (bf16 hi/lo 3-term) -> strip, fused row-max, softmax,
// mean-threshold mask, sparse P.V with 2 warps per row.
// ---------------------------------------------------------------------------
__global__ __launch_bounds__(1024, 1) void attn_kernel(float* __restrict__ out)
{
    extern __shared__ char smem[];
    float* sS   = (float*)(smem + OFF_S);
    int*   sIdx = (int*)(smem + OFF_K0);               // union with K buffers
    float* sM   = (float*)(smem + OFF_STAT);
    float* sL   = (float*)(smem + OFF_STAT + 64);
    int*   sCnt = (int*)(smem + OFF_STAT + 128);
    float* sLp  = (float*)(smem + OFF_STAT + 192);     // 16 x 2
    float* sMp  = (float*)(smem + OFF_STAT + 320);     // 16 x 32
    float* sPV  = (float*)(smem + OFF_STAT + 2368);    // 16 x 64

    uint32_t smem_base = smem_u32(smem);
    int tid  = threadIdx.x;
    int wid  = tid >> 5;
    int lane = tid & 31;
    int b    = blockIdx.y;
    int i0   = blockIdx.x * 16;

    int g    = wid >> 4;          // warp-group 0/1
    int gtid = tid & 511;
    uint32_t kbuf = smem_base + OFF_K0 + g * KBUF_SZ;

    // ---- stage this group's first chunk (chunk g) ----
    {
        const __nv_bfloat16* srcH = g_Kh + ((size_t)b * Nn + g * TK) * 64;
        const __nv_bfloat16* srcL = g_Kl + ((size_t)b * Nn + g * TK) * 64;
#pragma unroll
        for (int i = 0; i < 2; i++) {
            int slot = i * 512 + gtid;          // 1024 slots per split
            int row  = slot >> 3;
            int c16  = slot & 7;
            cp16(kbuf +         row * 144 + c16 * 16, srcH + row * 64 + c16 * 8);
            cp16(kbuf + KHALF + row * 144 + c16 * 16, srcL + row * 64 + c16 * 8);
        }
        CP_COMMIT();
    }

    // ---- stage Q tile [16][64] hi/lo ----
    if (tid < 256) {
        int half = tid >> 7;
        int t    = tid & 127;
        int row  = t >> 3;
        int c16  = t & 7;
        const __nv_bfloat16* src = (half ? g_Ql : g_Qh) + ((size_t)b * Nn + i0 + row) * 64 + c16 * 8;
        uint4 v = *(const uint4*)src;
        *(uint4*)(smem + (half ? OFF_QL : OFF_QH) + row * 144 + c16 * 16) = v;
    }
    __syncthreads();    // Q visible to all warps

    int n0 = (wid & 15) * 8;            // this warp's key group within a chunk
    int r0 = lane >> 2;
    float mx0 = -1e30f, mx1 = -1e30f;

    uint32_t baseA = smem_base + (uint32_t)((lane & 15) * 144 + (lane >> 4) * 16);
    uint32_t baseB = kbuf + (uint32_t)((n0 + (lane & 7)) * 144 + (lane >> 3) * 16);

    // ---- ping-pong main loop: group g handles chunks g, g+2, ..., g+14 ----
#pragma unroll 1
    for (int t = 0; t < 8; t++) {
        int c = g + 2 * t;
        CP_WAIT(0);
        GBAR(1 + g);                     // chunk c visible group-wide

        // B fragments
        uint32_t bh[8], bl[8];
        LDSM_X4(bh[0], bh[1], bh[2], bh[3], baseB);
        LDSM_X4(bh[4], bh[5], bh[6], bh[7], baseB + 64);
        LDSM_X4(bl[0], bl[1], bl[2], bl[3], baseB + KHALF);
        LDSM_X4(bl[4], bl[5], bl[6], bl[7], baseB + KHALF + 64);

        float d[4] = {0.f, 0.f, 0.f, 0.f};
        // term 1: Qh * Kh   and  term 3: Ql * Kh  (bh live), then term 2: Qh * Kl
        {
            uint32_t aH[16];
#pragma unroll
            for (int ks = 0; ks < 4; ks++)
                LDSM_X4(aH[ks * 4], aH[ks * 4 + 1], aH[ks * 4 + 2], aH[ks * 4 + 3],
                        baseA + OFF_QH + ks * 32);
#pragma unroll
            for (int ks = 0; ks < 4; ks++) mma16816(d, &aH[ks * 4], &bh[ks * 2]);
#pragma unroll
            for (int ks = 0; ks < 4; ks++) mma16816(d, &aH[ks * 4], &bl[ks * 2]);
        }
        {
            uint32_t aL[16];
#pragma unroll
            for (int ks = 0; ks < 4; ks++)
                LDSM_X4(aL[ks * 4], aL[ks * 4 + 1], aL[ks * 4 + 2], aL[ks * 4 + 3],
                        baseA + OFF_QL + ks * 32);
#pragma unroll
            for (int ks = 0; ks < 4; ks++) mma16816(d, &aL[ks * 4], &bh[ks * 2]);
        }

        mx0 = fmaxf(mx0, fmaxf(d[0], d[1]));
        mx1 = fmaxf(mx1, fmaxf(d[2], d[3]));

        int col = c * TK + n0 + (lane & 3) * 2;
        *(float2*)(sS + r0 * SSTR + col)       = make_float2(d[0], d[1]);
        *(float2*)(sS + (r0 + 8) * SSTR + col) = make_float2(d[2], d[3]);

        GBAR(1 + g);                     // group done reading kbuf
        if (t < 7) {
            int j0 = (c + 2) * TK;
            const __nv_bfloat16* srcH = g_Kh + ((size_t)b * Nn + j0) * 64;
            const __nv_bfloat16* srcL = g_Kl + ((size_t)b * Nn + j0) * 64;
#pragma unroll
            for (int i = 0; i < 2; i++) {
                int slot = i * 512 + gtid;
                int row  = slot >> 3;
                int c16  = slot & 7;
                cp16(kbuf +         row * 144 + c16 * 16, srcH + row * 64 + c16 * 8);
                cp16(kbuf + KHALF + row * 144 + c16 * 16, srcL + row * 64 + c16 * 8);
            }
            CP_COMMIT();
        }
    }

    // ---- fused row-max: quad shuffle + 32-warp partials + tree ----
    mx0 = fmaxf(mx0, __shfl_xor_sync(0xffffffffu, mx0, 1));
    mx0 = fmaxf(mx0, __shfl_xor_sync(0xffffffffu, mx0, 2));
    mx1 = fmaxf(mx1, __shfl_xor_sync(0xffffffffu, mx1, 1));
    mx1 = fmaxf(mx1, __shfl_xor_sync(0xffffffffu, mx1, 2));
    if ((lane & 3) == 0) {
        sMp[r0 * 32 + wid]       = mx0;
        sMp[(r0 + 8) * 32 + wid] = mx1;
    }
    __syncthreads();                     // strip complete + partials visible
    if (tid < 16) {
        float m = -1e30f;
#pragma unroll
        for (int w = 0; w < 32; w++) m = fmaxf(m, sMp[tid * 32 + w]);
        sM[tid] = m;
    }
    __syncthreads();

    // ---- pass B: e = exp(s - max), row sum (2 warps per row) ----
    {
        int row  = wid >> 1;
        int half = wid & 1;
        float M = sM[row];
        float sum = 0.f;
        int jbase = half * 1024;
#pragma unroll 4
        for (int j4 = jbase + lane * 4; j4 < jbase + 1024; j4 += 128) {
            float4 v = *(const float4*)(sS + row * SSTR + j4);
            v.x = __expf(v.x - M);
            v.y = __expf(v.y - M);
            v.z = __expf(v.z - M);
            v.w = __expf(v.w - M);
            sum += (v.x + v.y) + (v.z + v.w);
            *(float4*)(sS + row * SSTR + j4) = v;
        }
#pragma unroll
        for (int o = 16; o > 0; o >>= 1)
            sum += __shfl_xor_sync(0xffffffffu, sum, o);
        if (lane == 0) sLp[row * 2 + half] = sum;
    }
    __syncthreads();
    if (tid < 16) sL[tid] = sLp[tid * 2] + sLp[tid * 2 + 1];
    __syncthreads();

    // ---- pass C: mask (e > L/2048), ballot compaction (warps 0-15) ----
    if (wid < 16) {
        int row = wid;
        float thr = sL[row] * (1.0f / 2048.0f);
        unsigned lt = (1u << lane) - 1u;
        int cnt = 0;
        int* lst = sIdx + row * CAP;
#pragma unroll 1
        for (int cb = 0; cb < Nn; cb += 128) {
            int j = cb + lane * 4;
            float4 v = *(const float4*)(sS + row * SSTR + j);
            unsigned m0 = __ballot_sync(0xffffffffu, v.x > thr);
            unsigned m1 = __ballot_sync(0xffffffffu, v.y > thr);
            unsigned m2 = __ballot_sync(0xffffffffu, v.z > thr);
            unsigned m3 = __ballot_sync(0xffffffffu, v.w > thr);
            if (v.x > thr) { int p = cnt + __popc(m0 & lt); if (p < CAP) lst[p] = j; }
            cnt += __popc(m0);
            if (v.y > thr) { int p = cnt + __popc(m1 & lt); if (p < CAP) lst[p] = j + 1; }
            cnt += __popc(m1);
            if (v.z > thr) { int p = cnt + __popc(m2 & lt); if (p < CAP) lst[p] = j + 2; }
            cnt += __popc(m2);
            if (v.w > thr) { int p = cnt + __popc(m3 & lt); if (p < CAP) lst[p] = j + 3; }
            cnt += __popc(m3);
        }
        if (lane == 0) sCnt[row] = cnt;
    }
    __syncthreads();

    // ---- P.V: sparse gather, 2 warps per row (parity-interleaved list) ----
    {
        int r    = wid >> 1;
        int half = wid & 1;
        int tx   = lane * 2;
        int cnt  = sCnt[r];
        float Lr  = sL[r];
        float thr = Lr * (1.0f / 2048.0f);
        const float* vb   = g_V + (size_t)b * Nn * 64;
        const float* srow = sS + r * SSTR;
        float2 acc = make_float2(0.f, 0.f);

        if (cnt <= CAP) {
            const int* lst = sIdx + r * CAP;
            int i = half;
            for (; i + 6 < cnt; i += 8) {
                int k0 = lst[i], k1 = lst[i + 2], k2 = lst[i + 4], k3 = lst[i + 6];
                float w0 = srow[k0], w1 = srow[k1], w2 = srow[k2], w3 = srow[k3];
                float2 v0 = *(const float2*)(vb + (size_t)k0 * 64 + tx);
                float2 v1 = *(const float2*)(vb + (size_t)k1 * 64 + tx);
                float2 v2 = *(const float2*)(vb + (size_t)k2 * 64 + tx);
                float2 v3 = *(const float2*)(vb + (size_t)k3 * 64 + tx);
                acc.x += w0 * v0.x; acc.y += w0 * v0.y;
                acc.x += w1 * v1.x; acc.y += w1 * v1.y;
                acc.x += w2 * v2.x; acc.y += w2 * v2.y;
                acc.x += w3 * v3.x; acc.y += w3 * v3.y;
            }
            for (; i < cnt; i += 2) {
                int k = lst[i];
                float w = srow[k];
                float2 v = *(const float2*)(vb + (size_t)k * 64 + tx);
                acc.x += w * v.x; acc.y += w * v.y;
            }
        } else {
            int jbase = half * 1024;
            for (int k = jbase; k < jbase + 1024; k++) {
                float w = srow[k];
                if (w > thr) {
                    float2 v = *(const float2*)(vb + (size_t)k * 64 + tx);
                    acc.x += w * v.x; acc.y += w * v.y;
                }
            }
        }

        if (half == 0) *(float2*)(sPV + r * 64 + tx) = acc;
        __syncthreads();
        if (half == 1) {
            float2 p = *(const float2*)(sPV + r * 64 + tx);
            float invL = 1.0f / Lr;
            acc.x = (acc.x + p.x) * invL;
            acc.y = (acc.y + p.y) * invL;
            *(float2*)(out + ((size_t)b * Nn + i0 + r) * 64 + tx) = acc;
        }
    }
}

// ---------------------------------------------------------------------------
extern "C" void kernel_launch(void* const* d_in, const int* in_sizes, int n_in,
                              void* d_out, int out_size)
{
    const float* x  = (const float*)d_in[0];
    const float* Wq = (const float*)d_in[1];
    const float* bq = (const float*)d_in[2];
    const float* Wk = (const float*)d_in[3];
    const float* bk = (const float*)d_in[4];
    const float* Wv = (const float*)d_in[5];
    const float* bv = (const float*)d_in[6];
    float* out = (float*)d_out;

    cudaFuncSetAttribute(attn_kernel,
                         cudaFuncAttributeMaxDynamicSharedMemorySize, SMEM_TOTAL);

    qkv_kernel<<<(Bsz * Nn) / 64, 256>>>(x, Wq, bq, Wk, bk, Wv, bv);
    attn_kernel<<<dim3(Nn / 16, Bsz), 1024, SMEM_TOTAL>>>(out);
}

// round 6
// speedup vs baseline: 1.1693x; 1.1693x over previous
#include <cuda_runtime.h>
#include <cuda_bf16.h>
#include <cstdint>

#define Bsz 8
#define Nn 2048
#define SSTR 2052
#define CAP 1024
#define TK 128
#define SHIFT 32.0f

// ---------------- fused kernel smem layout (bytes) ----------------
#define OFF_S    0                   // 16 x 2052 fp32 strip = 131,328
#define OFF_K0   131328              // 2 x (KH 128x144 + KL 128x144) = 73,728
#define KBUF_SZ  36864
#define KHALF    18432
#define OFF_QH   205056
#define OFF_QL   207360              // each Q split 16x144 = 2,304
#define OFF_STAT 209664              // sL 64 | sCnt 64 | sLp 1024
#define SMEM_TOTAL 210816

__device__ float          g_V [Bsz * Nn * 64];
__device__ __nv_bfloat16  g_Qh[Bsz * Nn * 64];
__device__ __nv_bfloat16  g_Ql[Bsz * Nn * 64];
__device__ __nv_bfloat16  g_Kh[Bsz * Nn * 64];
__device__ __nv_bfloat16  g_Kl[Bsz * Nn * 64];

// ================= helpers =================
__device__ __forceinline__ uint32_t smem_u32(const void* p) {
    uint32_t a;
    asm("{ .reg .u64 t; cvta.to.shared.u64 t, %1; cvt.u32.u64 %0, t; }" : "=r"(a) : "l"(p));
    return a;
}
__device__ __forceinline__ void cp16(uint32_t dst, const void* src) {
    asm volatile("cp.async.cg.shared.global [%0], [%1], 16;" :: "r"(dst), "l"(src));
}
#define CP_COMMIT()  asm volatile("cp.async.commit_group;" ::: "memory")
#define CP_WAIT(n)   asm volatile("cp.async.wait_group %0;" :: "n"(n) : "memory")

#define LDSM_X4(r0, r1, r2, r3, addr)                                          \
    asm volatile("ldmatrix.sync.aligned.m8n8.x4.shared.b16 {%0,%1,%2,%3}, [%4];" \
        : "=r"(r0), "=r"(r1), "=r"(r2), "=r"(r3) : "r"(addr))

__device__ __forceinline__ void mma16816(float* d, const uint32_t* a, const uint32_t* b) {
    asm volatile(
        "mma.sync.aligned.m16n8k16.row.col.f32.bf16.bf16.f32 "
        "{%0,%1,%2,%3}, {%4,%5,%6,%7}, {%8,%9}, {%0,%1,%2,%3};"
        : "+f"(d[0]), "+f"(d[1]), "+f"(d[2]), "+f"(d[3])
        : "r"(a[0]), "r"(a[1]), "r"(a[2]), "r"(a[3]), "r"(b[0]), "r"(b[1]));
}

// ---------------------------------------------------------------------------
// Kernel A: QKV projection -> bf16 hi/lo Q,K splits + fp32 V.
// ---------------------------------------------------------------------------
__global__ __launch_bounds__(256) void qkv_kernel(
    const float* __restrict__ x,
    const float* __restrict__ Wq, const float* __restrict__ bq,
    const float* __restrict__ Wk, const float* __restrict__ bk,
    const float* __restrict__ Wv, const float* __restrict__ bv)
{
    __shared__ float sX[64 * 68];
    int tid = threadIdx.x;
    size_t base = (size_t)blockIdx.x * 64;

#pragma unroll
    for (int i = 0; i < 4; i++) {
        int slot = i * 256 + tid;
        int row  = slot >> 4;
        int d4   = (slot & 15) << 2;
        float4 v = *(const float4*)(x + (base + row) * 64 + d4);
        *(float4*)(sX + row * 68 + d4) = v;
    }
    __syncthreads();

    int c  = tid & 63;
    int rg = tid >> 6;

#pragma unroll 1
    for (int m = 0; m < 3; m++) {
        const float* W  = (m == 0) ? Wq : (m == 1) ? Wk : Wv;
        const float* bb = (m == 0) ? bq : (m == 1) ? bk : bv;
        float wcol[64];
#pragma unroll
        for (int d = 0; d < 64; d++) wcol[d] = W[d * 64 + c];
        float bias = bb[c];

#pragma unroll 1
        for (int rr = 0; rr < 16; rr++) {
            int r = rg * 16 + rr;
            const float* xr = sX + r * 68;
            float a0 = 0.f, a1 = 0.f, a2 = 0.f, a3 = 0.f;
#pragma unroll
            for (int d = 0; d < 64; d += 4) {
                float4 xv = *(const float4*)(xr + d);
                a0 += xv.x * wcol[d];
                a1 += xv.y * wcol[d + 1];
                a2 += xv.z * wcol[d + 2];
                a3 += xv.w * wcol[d + 3];
            }
            float acc = ((a0 + a1) + (a2 + a3)) + bias;
            size_t idx = (base + r) * 64 + c;
            if (m == 2) {
                g_V[idx] = acc;
            } else {
                __nv_bfloat16 hi = __float2bfloat16(acc);
                __nv_bfloat16 lo = __float2bfloat16(acc - __bfloat162float(hi));
                if (m == 0) { g_Qh[idx] = hi; g_Ql[idx] = lo; }
                else        { g_Kh[idx] = hi; g_Kl[idx] = lo; }
            }
        }
    }
}

// ---------------------------------------------------------------------------
// Kernel B (fused): HMMA scores (bf16 hi/lo 3-term, dual accumulator chains)
// with exp + row-sum FUSED into the GEMM epilogue (constant shift, softmax is
// shift-invariant). Then mean-threshold mask + sparse P.V.
// Block = (batch, 16 query rows), 512 threads, ~206 KB smem.
// ---------------------------------------------------------------------------
__global__ __launch_bounds__(512, 1) void attn_kernel(float* __restrict__ out)
{
    extern __shared__ char smem[];
    float* sS   = (float*)(smem + OFF_S);
    int*   sIdx = (int*)(smem + OFF_K0);          // union with K buffers
    float* sL   = (float*)(smem + OFF_STAT);
    int*   sCnt = (int*)(smem + OFF_STAT + 64);
    float* sLp  = (float*)(smem + OFF_STAT + 128); // 16 rows x 16 warps

    uint32_t smem_base = smem_u32(smem);
    int tid  = threadIdx.x;
    int wid  = tid >> 5;
    int lane = tid & 31;
    int b    = blockIdx.y;
    int i0   = blockIdx.x * 16;

    // ---- stage chunk 0 of K ----
    {
        uint32_t kb = smem_base + OFF_K0;
        const __nv_bfloat16* srcH = g_Kh + ((size_t)b * Nn) * 64;
        const __nv_bfloat16* srcL = g_Kl + ((size_t)b * Nn) * 64;
#pragma unroll
        for (int i = 0; i < 2; i++) {
            int slot = i * 512 + tid;           // 1024 slots per split
            int row  = slot >> 3;
            int c16  = slot & 7;
            cp16(kb +         row * 144 + c16 * 16, srcH + row * 64 + c16 * 8);
            cp16(kb + KHALF + row * 144 + c16 * 16, srcL + row * 64 + c16 * 8);
        }
        CP_COMMIT();
    }

    // ---- stage Q tile [16][64] hi/lo ----
    if (tid < 256) {
        int half = tid >> 7;
        int t    = tid & 127;
        int row  = t >> 3;
        int c16  = t & 7;
        const __nv_bfloat16* src = (half ? g_Ql : g_Qh) + ((size_t)b * Nn + i0 + row) * 64 + c16 * 8;
        uint4 v = *(const uint4*)src;
        *(uint4*)(smem + (half ? OFF_QL : OFF_QH) + row * 144 + c16 * 16) = v;
    }
    __syncthreads();

    // ---- A fragments via ldmatrix (resident): 4 k-steps x 4 regs, hi + lo ----
    uint32_t aH[16], aL[16];
    {
        uint32_t baseA = (lane & 15) * 144 + (lane >> 4) * 16;
#pragma unroll
        for (int ks = 0; ks < 4; ks++) {
            LDSM_X4(aH[ks * 4], aH[ks * 4 + 1], aH[ks * 4 + 2], aH[ks * 4 + 3],
                    smem_base + OFF_QH + baseA + ks * 32);
            LDSM_X4(aL[ks * 4], aL[ks * 4 + 1], aL[ks * 4 + 2], aL[ks * 4 + 3],
                    smem_base + OFF_QL + baseA + ks * 32);
        }
    }

    int n0 = wid * 8;                        // this warp's key group within chunk
    int r0 = lane >> 2;
    float sum0 = 0.f, sum1 = 0.f;            // partial exp-sums for rows r0, r0+8

    // ---- main loop: 16 key chunks of 128, double-buffered ----
#pragma unroll 1
    for (int c = 0; c < 16; c++) {
        if (c < 15) {
            uint32_t kb = smem_base + OFF_K0 + ((c + 1) & 1) * KBUF_SZ;
            int j0 = (c + 1) * TK;
            const __nv_bfloat16* srcH = g_Kh + ((size_t)b * Nn + j0) * 64;
            const __nv_bfloat16* srcL = g_Kl + ((size_t)b * Nn + j0) * 64;
#pragma unroll
            for (int i = 0; i < 2; i++) {
                int slot = i * 512 + tid;
                int row  = slot >> 3;
                int c16  = slot & 7;
                cp16(kb +         row * 144 + c16 * 16, srcH + row * 64 + c16 * 8);
                cp16(kb + KHALF + row * 144 + c16 * 16, srcL + row * 64 + c16 * 8);
            }
            CP_COMMIT();
            CP_WAIT(1);
        } else {
            CP_WAIT(0);
        }
        __syncthreads();

        uint32_t kh = smem_base + OFF_K0 + (c & 1) * KBUF_SZ
                    + (uint32_t)(n0 + (lane & 7)) * 144 + (uint32_t)(lane >> 3) * 16;
        uint32_t kl = kh + KHALF;

        uint32_t bh[8], bl[8];
        LDSM_X4(bh[0], bh[1], bh[2], bh[3], kh);
        LDSM_X4(bh[4], bh[5], bh[6], bh[7], kh + 64);
        LDSM_X4(bl[0], bl[1], bl[2], bl[3], kl);
        LDSM_X4(bl[4], bl[5], bl[6], bl[7], kl + 64);

        // two independent accumulator chains (even/odd k-step)
        float d0[4] = {0.f, 0.f, 0.f, 0.f};
        float d1[4] = {0.f, 0.f, 0.f, 0.f};
        mma16816(d0, &aH[0],  &bh[0]);  mma16816(d1, &aH[4],  &bh[2]);
        mma16816(d0, &aH[8],  &bh[4]);  mma16816(d1, &aH[12], &bh[6]);
        mma16816(d0, &aH[0],  &bl[0]);  mma16816(d1, &aH[4],  &bl[2]);
        mma16816(d0, &aH[8],  &bl[4]);  mma16816(d1, &aH[12], &bl[6]);
        mma16816(d0, &aL[0],  &bh[0]);  mma16816(d1, &aL[4],  &bh[2]);
        mma16816(d0, &aL[8],  &bh[4]);  mma16816(d1, &aL[12], &bh[6]);

        // fused epilogue: exp with constant shift, accumulate row sums
        float e0 = __expf((d0[0] + d1[0]) - SHIFT);
        float e1 = __expf((d0[1] + d1[1]) - SHIFT);
        float e2 = __expf((d0[2] + d1[2]) - SHIFT);
        float e3 = __expf((d0[3] + d1[3]) - SHIFT);
        sum0 += e0 + e1;
        sum1 += e2 + e3;

        int col = c * TK + n0 + (lane & 3) * 2;
        *(float2*)(sS + r0 * SSTR + col)       = make_float2(e0, e1);
        *(float2*)(sS + (r0 + 8) * SSTR + col) = make_float2(e2, e3);
        __syncthreads();
    }

    // ---- row-sum reduction: quad shuffle -> per-warp partials -> tree ----
    sum0 += __shfl_xor_sync(0xffffffffu, sum0, 1);
    sum0 += __shfl_xor_sync(0xffffffffu, sum0, 2);
    sum1 += __shfl_xor_sync(0xffffffffu, sum1, 1);
    sum1 += __shfl_xor_sync(0xffffffffu, sum1, 2);
    if ((lane & 3) == 0) {
        sLp[r0 * 16 + wid]       = sum0;
        sLp[(r0 + 8) * 16 + wid] = sum1;
    }
    __syncthreads();
    if (tid < 16) {
        float s = 0.f;
#pragma unroll
        for (int w = 0; w < 16; w++) s += sLp[tid * 16 + w];
        sL[tid] = s;
    }
    __syncthreads();

    // ---- mask pass: e > L/2048, ballot compaction, no zero-writeback ----
    {
        int row = wid;
        float thr = sL[row] * (1.0f / 2048.0f);
        unsigned lt = (1u << lane) - 1u;
        int cnt = 0;
        int* lst = sIdx + row * CAP;
#pragma unroll 1
        for (int cb = 0; cb < Nn; cb += 128) {
            int j = cb + lane * 4;
            float4 v = *(const float4*)(sS + row * SSTR + j);
            unsigned m0 = __ballot_sync(0xffffffffu, v.x > thr);
            unsigned m1 = __ballot_sync(0xffffffffu, v.y > thr);
            unsigned m2 = __ballot_sync(0xffffffffu, v.z > thr);
            unsigned m3 = __ballot_sync(0xffffffffu, v.w > thr);
            if (v.x > thr) { int p = cnt + __popc(m0 & lt); if (p < CAP) lst[p] = j; }
            cnt += __popc(m0);
            if (v.y > thr) { int p = cnt + __popc(m1 & lt); if (p < CAP) lst[p] = j + 1; }
            cnt += __popc(m1);
            if (v.z > thr) { int p = cnt + __popc(m2 & lt); if (p < CAP) lst[p] = j + 2; }
            cnt += __popc(m2);
            if (v.w > thr) { int p = cnt + __popc(m3 & lt); if (p < CAP) lst[p] = j + 3; }
            cnt += __popc(m3);
        }
        if (lane == 0) sCnt[row] = cnt;
    }
    __syncthreads();

    // ---- P.V: sparse gather of V rows (32 lanes per row, float2) ----
    {
        int r  = tid >> 5;
        int tx = lane * 2;
        int cnt = sCnt[r];
        float Lr = sL[r];
        float invL = 1.0f / Lr;
        float thr = Lr * (1.0f / 2048.0f);
        const float* vb   = g_V + (size_t)b * Nn * 64;
        const float* srow = sS + r * SSTR;
        float2 acc = make_float2(0.f, 0.f);

        if (cnt <= CAP) {
            const int* lst = sIdx + r * CAP;
            int i = 0;
            for (; i + 4 <= cnt; i += 4) {
                int k0 = lst[i], k1 = lst[i + 1], k2 = lst[i + 2], k3 = lst[i + 3];
                float w0 = srow[k0], w1 = srow[k1], w2 = srow[k2], w3 = srow[k3];
                float2 v0 = *(const float2*)(vb + (size_t)k0 * 64 + tx);
                float2 v1 = *(const float2*)(vb + (size_t)k1 * 64 + tx);
                float2 v2 = *(const float2*)(vb + (size_t)k2 * 64 + tx);
                float2 v3 = *(const float2*)(vb + (size_t)k3 * 64 + tx);
                acc.x += w0 * v0.x; acc.y += w0 * v0.y;
                acc.x += w1 * v1.x; acc.y += w1 * v1.y;
                acc.x += w2 * v2.x; acc.y += w2 * v2.y;
                acc.x += w3 * v3.x; acc.y += w3 * v3.y;
            }
            for (; i < cnt; i++) {
                int k = lst[i];
                float w = srow[k];
                float2 v = *(const float2*)(vb + (size_t)k * 64 + tx);
                acc.x += w * v.x; acc.y += w * v.y;
            }
        } else {
            for (int k = 0; k < Nn; k++) {
                float w = srow[k];
                if (w > thr) {
                    float2 v = *(const float2*)(vb + (size_t)k * 64 + tx);
                    acc.x += w * v.x; acc.y += w * v.y;
                }
            }
        }

        acc.x *= invL; acc.y *= invL;
        *(float2*)(out + ((size_t)b * Nn + i0 + r) * 64 + tx) = acc;
    }
}

// ---------------------------------------------------------------------------
extern "C" void kernel_launch(void* const* d_in, const int* in_sizes, int n_in,
                              void* d_out, int out_size)
{
    const float* x  = (const float*)d_in[0];
    const float* Wq = (const float*)d_in[1];
    const float* bq = (const float*)d_in[2];
    const float* Wk = (const float*)d_in[3];
    const float* bk = (const float*)d_in[4];
    const float* Wv = (const float*)d_in[5];
    const float* bv = (const float*)d_in[6];
    float* out = (float*)d_out;

    cudaFuncSetAttribute(attn_kernel,
                         cudaFuncAttributeMaxDynamicSharedMemorySize, SMEM_TOTAL);

    qkv_kernel<<<(Bsz * Nn) / 64, 256>>>(x, Wq, bq, Wk, bk, Wv, bv);
    attn_kernel<<<dim3(Nn / 16, Bsz), 512, SMEM_TOTAL>>>(out);
}

// round 7
// speedup vs baseline: 1.2350x; 1.0562x over previous
#include <cuda_runtime.h>
#include <cuda_bf16.h>
#include <cstdint>

#define Bsz 8
#define Nn 2048
#define Mr 32                 // q rows per CTA
#define CAP 128               // per-row sparse list capacity
#define POOLCAP 512           // shared overflow pool
#define TK 128
#define SHIFT 32.0f

// ---------------- attn smem layout (bytes) ----------------
#define OFF_K    0            // 2 bufs x (KH 128x128B + KL 128x128B)
#define KBUF     32768
#define KHALF    16384
#define OFF_Q    65536        // QH 32x128B, QL 32x128B
#define OFF_LIST 73728        // 32 rows x CAP x float2 = 32768
#define OFF_POOL 106496       // 512 x float2 = 4096
#define OFF_STAT 110592       // sL 128 | sLp 1024 | sCnt 128 | poolCnt 16
#define SMEM_TOTAL 111904

__device__ float          g_V [Bsz * Nn * 64];
__device__ __nv_bfloat16  g_Qh[Bsz * Nn * 64];
__device__ __nv_bfloat16  g_Ql[Bsz * Nn * 64];
__device__ __nv_bfloat16  g_Kh[Bsz * Nn * 64];
__device__ __nv_bfloat16  g_Kl[Bsz * Nn * 64];

// ================= helpers =================
__device__ __forceinline__ uint32_t smem_u32(const void* p) {
    uint32_t a;
    asm("{ .reg .u64 t; cvta.to.shared.u64 t, %1; cvt.u32.u64 %0, t; }" : "=r"(a) : "l"(p));
    return a;
}
__device__ __forceinline__ void cp16(uint32_t dst, const void* src) {
    asm volatile("cp.async.cg.shared.global [%0], [%1], 16;" :: "r"(dst), "l"(src));
}
#define CP_COMMIT()  asm volatile("cp.async.commit_group;" ::: "memory")
#define CP_WAIT(n)   asm volatile("cp.async.wait_group %0;" :: "n"(n) : "memory")
#define SW128(off)   ((off) ^ (((off) >> 3) & 0x70))

#define LDSM_X4(r0, r1, r2, r3, addr)                                          \
    asm volatile("ldmatrix.sync.aligned.m8n8.x4.shared.b16 {%0,%1,%2,%3}, [%4];" \
        : "=r"(r0), "=r"(r1), "=r"(r2), "=r"(r3) : "r"(addr))

__device__ __forceinline__ void mma16816(float* d, const uint32_t* a, const uint32_t* b) {
    asm volatile(
        "mma.sync.aligned.m16n8k16.row.col.f32.bf16.bf16.f32 "
        "{%0,%1,%2,%3}, {%4,%5,%6,%7}, {%8,%9}, {%0,%1,%2,%3};"
        : "+f"(d[0]), "+f"(d[1]), "+f"(d[2]), "+f"(d[3])
        : "r"(a[0]), "r"(a[1]), "r"(a[2]), "r"(a[3]), "r"(b[0]), "r"(b[1]));
}

// ---------------------------------------------------------------------------
// Kernel A: QKV projection -> bf16 hi/lo Q,K splits + fp32 V. (unchanged)
// ---------------------------------------------------------------------------
__global__ __launch_bounds__(256) void qkv_kernel(
    const float* __restrict__ x,
    const float* __restrict__ Wq, const float* __restrict__ bq,
    const float* __restrict__ Wk, const float* __restrict__ bk,
    const float* __restrict__ Wv, const float* __restrict__ bv)
{
    __shared__ float sX[64 * 68];
    int tid = threadIdx.x;
    size_t base = (size_t)blockIdx.x * 64;

#pragma unroll
    for (int i = 0; i < 4; i++) {
        int slot = i * 256 + tid;
        int row  = slot >> 4;
        int d4   = (slot & 15) << 2;
        float4 v = *(const float4*)(x + (base + row) * 64 + d4);
        *(float4*)(sX + row * 68 + d4) = v;
    }
    __syncthreads();

    int c  = tid & 63;
    int rg = tid >> 6;

#pragma unroll 1
    for (int m = 0; m < 3; m++) {
        const float* W  = (m == 0) ? Wq : (m == 1) ? Wk : Wv;
        const float* bb = (m == 0) ? bq : (m == 1) ? bk : bv;
        float wcol[64];
#pragma unroll
        for (int d = 0; d < 64; d++) wcol[d] = W[d * 64 + c];
        float bias = bb[c];

#pragma unroll 1
        for (int rr = 0; rr < 16; rr++) {
            int r = rg * 16 + rr;
            const float* xr = sX + r * 68;
            float a0 = 0.f, a1 = 0.f, a2 = 0.f, a3 = 0.f;
#pragma unroll
            for (int d = 0; d < 64; d += 4) {
                float4 xv = *(const float4*)(xr + d);
                a0 += xv.x * wcol[d];
                a1 += xv.y * wcol[d + 1];
                a2 += xv.z * wcol[d + 2];
                a3 += xv.w * wcol[d + 3];
            }
            float acc = ((a0 + a1) + (a2 + a3)) + bias;
            size_t idx = (base + r) * 64 + c;
            if (m == 2) {
                g_V[idx] = acc;
            } else {
                __nv_bfloat16 hi = __float2bfloat16(acc);
                __nv_bfloat16 lo = __float2bfloat16(acc - __bfloat162float(hi));
                if (m == 0) { g_Qh[idx] = hi; g_Ql[idx] = lo; }
                else        { g_Kh[idx] = hi; g_Kl[idx] = lo; }
            }
        }
    }
}

// ---------------------------------------------------------------------------
// Kernel B: two-pass stripless attention. M=32 rows/CTA, 256 threads, 2 CTA/SM.
// Pass 1 (iters 0-15): scores -> exp -> row sums.  Pass 2 (16-31): recompute,
// mask e > L/2048 in registers, atomic-append survivors to per-row lists.
// Then sparse P.V from lists.
// ---------------------------------------------------------------------------
__global__ __launch_bounds__(256, 2) void attn_kernel(float* __restrict__ out)
{
    extern __shared__ char smem[];
    float2* sList = (float2*)(smem + OFF_LIST);
    float2* sPool = (float2*)(smem + OFF_POOL);
    float*  sL    = (float*)(smem + OFF_STAT);
    float*  sLp   = (float*)(smem + OFF_STAT + 128);
    int*    sCnt  = (int*)(smem + OFF_STAT + 1152);
    int*    sPoolCnt = (int*)(smem + OFF_STAT + 1280);

    uint32_t sb = smem_u32(smem);
    int tid  = threadIdx.x;
    int wid  = tid >> 5;
    int lane = tid & 31;
    int b    = blockIdx.y;
    int i0   = blockIdx.x * Mr;

    if (tid < 32) sCnt[tid] = 0;
    if (tid == 0) *sPoolCnt = 0;

    // ---- stage chunk 0 of K into buffer 0 ----
    {
        const __nv_bfloat16* srcH = g_Kh + (size_t)b * Nn * 64;
        const __nv_bfloat16* srcL = g_Kl + (size_t)b * Nn * 64;
#pragma unroll
        for (int i = 0; i < 4; i++) {
            int slot = i * 256 + tid;              // 1024 slots per half
            int row  = slot >> 3;
            int c16  = slot & 7;
            uint32_t sw = SW128((uint32_t)(row * 128 + c16 * 16));
            cp16(sb + OFF_K + sw,         srcH + row * 64 + c16 * 8);
            cp16(sb + OFF_K + KHALF + sw, srcL + row * 64 + c16 * 8);
        }
        CP_COMMIT();
    }

    // ---- stage Q tile [32][64] hi/lo, SW128 128B rows ----
#pragma unroll
    for (int i = 0; i < 2; i++) {
        int slot = i * 256 + tid;                  // 512 slots
        int half = slot >> 8;
        int t    = slot & 255;
        int row  = t >> 3;
        int c16  = t & 7;
        const __nv_bfloat16* src = (half ? g_Ql : g_Qh) + ((size_t)b * Nn + i0 + row) * 64 + c16 * 8;
        uint4 v = *(const uint4*)src;
        *(uint4*)(smem + OFF_Q + half * 4096 + SW128((uint32_t)(row * 128 + c16 * 16))) = v;
    }
    __syncthreads();

    // ---- resident A fragments: 2 m-tiles x 4 ksteps x 4 regs, hi + lo ----
    uint32_t aH[2][16], aL[2][16];
#pragma unroll
    for (int mt = 0; mt < 2; mt++)
#pragma unroll
        for (int ks = 0; ks < 4; ks++) {
            uint32_t off = (uint32_t)((mt * 16 + (lane & 15)) * 128 + (ks * 2 + (lane >> 4)) * 16);
            LDSM_X4(aH[mt][ks*4], aH[mt][ks*4+1], aH[mt][ks*4+2], aH[mt][ks*4+3],
                    sb + OFF_Q + SW128(off));
            LDSM_X4(aL[mt][ks*4], aL[mt][ks*4+1], aL[mt][ks*4+2], aL[mt][ks*4+3],
                    sb + OFF_Q + 4096 + SW128(off));
        }

    int w16 = wid * 16;
    int r0  = lane >> 2;
    float sums[4] = {0.f, 0.f, 0.f, 0.f};          // rows r0, r0+8, r0+16, r0+24
    float thrv[4];

    // ---- unified loop: iters 0-15 = pass 1, 16-31 = pass 2 ----
#pragma unroll 1
    for (int it = 0; it < 32; it++) {
        if (it < 31) {
            int c = (it + 1) & 15;
            uint32_t kb = sb + OFF_K + ((it + 1) & 1) * KBUF;
            const __nv_bfloat16* srcH = g_Kh + ((size_t)b * Nn + c * TK) * 64;
            const __nv_bfloat16* srcL = g_Kl + ((size_t)b * Nn + c * TK) * 64;
#pragma unroll
            for (int i = 0; i < 4; i++) {
                int slot = i * 256 + tid;
                int row  = slot >> 3;
                int c16  = slot & 7;
                uint32_t sw = SW128((uint32_t)(row * 128 + c16 * 16));
                cp16(kb + sw,         srcH + row * 64 + c16 * 8);
                cp16(kb + KHALF + sw, srcL + row * 64 + c16 * 8);
            }
            CP_COMMIT();
            CP_WAIT(1);
        } else {
            CP_WAIT(0);
        }
        __syncthreads();

        uint32_t kb = sb + OFF_K + (it & 1) * KBUF;
        int chunk = it & 15;

#pragma unroll
        for (int nt = 0; nt < 2; nt++) {
            uint32_t rowoff = (uint32_t)((w16 + nt * 8 + (lane & 7)) * 128 + (lane >> 3) * 16);
            uint32_t bh[8], bl[8];
            LDSM_X4(bh[0], bh[1], bh[2], bh[3], kb + SW128(rowoff));
            LDSM_X4(bh[4], bh[5], bh[6], bh[7], kb + SW128(rowoff + 64));
            LDSM_X4(bl[0], bl[1], bl[2], bl[3], kb + KHALF + SW128(rowoff));
            LDSM_X4(bl[4], bl[5], bl[6], bl[7], kb + KHALF + SW128(rowoff + 64));

#pragma unroll
            for (int mt = 0; mt < 2; mt++) {
                float d0[4] = {0.f, 0.f, 0.f, 0.f};
                float d1[4] = {0.f, 0.f, 0.f, 0.f};
                mma16816(d0, &aH[mt][0],  &bh[0]);  mma16816(d1, &aH[mt][4],  &bh[2]);
                mma16816(d0, &aH[mt][8],  &bh[4]);  mma16816(d1, &aH[mt][12], &bh[6]);
                mma16816(d0, &aH[mt][0],  &bl[0]);  mma16816(d1, &aH[mt][4],  &bl[2]);
                mma16816(d0, &aH[mt][8],  &bl[4]);  mma16816(d1, &aH[mt][12], &bl[6]);
                mma16816(d0, &aL[mt][0],  &bh[0]);  mma16816(d1, &aL[mt][4],  &bh[2]);
                mma16816(d0, &aL[mt][8],  &bh[4]);  mma16816(d1, &aL[mt][12], &bh[6]);

                float e0 = __expf((d0[0] + d1[0]) - SHIFT);
                float e1 = __expf((d0[1] + d1[1]) - SHIFT);
                float e2 = __expf((d0[2] + d1[2]) - SHIFT);
                float e3 = __expf((d0[3] + d1[3]) - SHIFT);

                if (it < 16) {
                    sums[mt * 2 + 0] += e0 + e1;
                    sums[mt * 2 + 1] += e2 + e3;
                } else {
                    int ra = mt * 16 + r0, rb = ra + 8;
                    int j0 = chunk * TK + w16 + nt * 8 + (lane & 3) * 2;
                    float ta = thrv[mt * 2], tb = thrv[mt * 2 + 1];
                    if (e0 > ta) {
                        int p = atomicAdd(&sCnt[ra], 1);
                        if (p < CAP) sList[ra * CAP + p] = make_float2(e0, __int_as_float(j0));
                        else { int gq = atomicAdd(sPoolCnt, 1); if (gq < POOLCAP) sPool[gq] = make_float2(e0, __int_as_float((ra << 11) | j0)); }
                    }
                    if (e1 > ta) {
                        int p = atomicAdd(&sCnt[ra], 1);
                        if (p < CAP) sList[ra * CAP + p] = make_float2(e1, __int_as_float(j0 + 1));
                        else { int gq = atomicAdd(sPoolCnt, 1); if (gq < POOLCAP) sPool[gq] = make_float2(e1, __int_as_float((ra << 11) | (j0 + 1))); }
                    }
                    if (e2 > tb) {
                        int p = atomicAdd(&sCnt[rb], 1);
                        if (p < CAP) sList[rb * CAP + p] = make_float2(e2, __int_as_float(j0));
                        else { int gq = atomicAdd(sPoolCnt, 1); if (gq < POOLCAP) sPool[gq] = make_float2(e2, __int_as_float((rb << 11) | j0)); }
                    }
                    if (e3 > tb) {
                        int p = atomicAdd(&sCnt[rb], 1);
                        if (p < CAP) sList[rb * CAP + p] = make_float2(e3, __int_as_float(j0 + 1));
                        else { int gq = atomicAdd(sPoolCnt, 1); if (gq < POOLCAP) sPool[gq] = make_float2(e3, __int_as_float((rb << 11) | (j0 + 1))); }
                    }
                }
            }
        }
        __syncthreads();

        if (it == 15) {
            // reduce row sums -> L, derive thresholds
#pragma unroll
            for (int s = 0; s < 4; s++) {
                sums[s] += __shfl_xor_sync(0xffffffffu, sums[s], 1);
                sums[s] += __shfl_xor_sync(0xffffffffu, sums[s], 2);
            }
            if ((lane & 3) == 0) {
                sLp[(r0     ) * 8 + wid] = sums[0];
                sLp[(r0 +  8) * 8 + wid] = sums[1];
                sLp[(r0 + 16) * 8 + wid] = sums[2];
                sLp[(r0 + 24) * 8 + wid] = sums[3];
            }
            __syncthreads();
            if (tid < 32) {
                float s = 0.f;
#pragma unroll
                for (int wd = 0; wd < 8; wd++) s += sLp[tid * 8 + wd];
                sL[tid] = s;
            }
            __syncthreads();
            thrv[0] = sL[r0]      * (1.0f / 2048.0f);
            thrv[1] = sL[r0 + 8]  * (1.0f / 2048.0f);
            thrv[2] = sL[r0 + 16] * (1.0f / 2048.0f);
            thrv[3] = sL[r0 + 24] * (1.0f / 2048.0f);
        }
    }

    // ---- P.V: sparse gather from lists; warp handles 4 rows ----
    const float* vb = g_V + (size_t)b * Nn * 64;
    int tx = lane * 2;
#pragma unroll 1
    for (int rr = 0; rr < 4; rr++) {
        int r = wid * 4 + rr;
        int cnt = sCnt[r];
        int cl  = cnt < CAP ? cnt : CAP;
        float Lr = sL[r];
        const float2* lst = sList + r * CAP;
        float2 acc = make_float2(0.f, 0.f);

        int i = 0;
        for (; i + 4 <= cl; i += 4) {
            float2 p0 = lst[i], p1 = lst[i + 1], p2 = lst[i + 2], p3 = lst[i + 3];
            int j0 = __float_as_int(p0.y), j1 = __float_as_int(p1.y);
            int j2 = __float_as_int(p2.y), j3 = __float_as_int(p3.y);
            float2 v0 = *(const float2*)(vb + (size_t)j0 * 64 + tx);
            float2 v1 = *(const float2*)(vb + (size_t)j1 * 64 + tx);
            float2 v2 = *(const float2*)(vb + (size_t)j2 * 64 + tx);
            float2 v3 = *(const float2*)(vb + (size_t)j3 * 64 + tx);
            acc.x += p0.x * v0.x; acc.y += p0.x * v0.y;
            acc.x += p1.x * v1.x; acc.y += p1.x * v1.y;
            acc.x += p2.x * v2.x; acc.y += p2.x * v2.y;
            acc.x += p3.x * v3.x; acc.y += p3.x * v3.y;
        }
        for (; i < cl; i++) {
            float2 p = lst[i];
            int j = __float_as_int(p.y);
            float2 v = *(const float2*)(vb + (size_t)j * 64 + tx);
            acc.x += p.x * v.x; acc.y += p.x * v.y;
        }
        if (cnt > CAP) {
            int pc = *sPoolCnt;
            if (pc > POOLCAP) pc = POOLCAP;
            for (int k = 0; k < pc; k++) {
                float2 p = sPool[k];
                int idx = __float_as_int(p.y);
                if ((idx >> 11) == r) {
                    int j = idx & 2047;
                    float2 v = *(const float2*)(vb + (size_t)j * 64 + tx);
                    acc.x += p.x * v.x; acc.y += p.x * v.y;
                }
            }
        }

        float invL = 1.0f / Lr;
        *(float2*)(out + ((size_t)b * Nn + i0 + r) * 64 + tx) =
            make_float2(acc.x * invL, acc.y * invL);
    }
}

// ---------------------------------------------------------------------------
extern "C" void kernel_launch(void* const* d_in, const int* in_sizes, int n_in,
                              void* d_out, int out_size)
{
    const float* x  = (const float*)d_in[0];
    const float* Wq = (const float*)d_in[1];
    const float* bq = (const float*)d_in[2];
    const float* Wk = (const float*)d_in[3];
    const float* bk = (const float*)d_in[4];
    const float* Wv = (const float*)d_in[5];
    const float* bv = (const float*)d_in[6];
    float* out = (float*)d_out;

    cudaFuncSetAttribute(attn_kernel,
                         cudaFuncAttributeMaxDynamicSharedMemorySize, SMEM_TOTAL);

    qkv_kernel<<<(Bsz * Nn) / 64, 256>>>(x, Wq, bq, Wk, bk, Wv, bv);
    attn_kernel<<<dim3(Nn / Mr, Bsz), 256, SMEM_TOTAL>>>(out);
}

// round 8
// speedup vs baseline: 1.2539x; 1.0153x over previous
#include <cuda_runtime.h>
#include <cuda_bf16.h>
#include <cstdint>

#define Bsz 8
#define Nn 2048
#define Mr 32                 // q rows per CTA
#define CAP 128               // per-row sparse list capacity
#define POOLCAP 512           // shared overflow pool
#define SHIFT 32.0f

// ---------------- attn smem layout (bytes) ----------------
// per-warp K region: 2 bufs x (hi 16x128B + lo 16x128B) = 8192 B
#define OFF_K    0            // 8 warps x 8192 = 65536
#define OFF_Q    65536        // QH 4096 + QL 4096
#define OFF_LIST 73728        // 32 rows x CAP x float2 = 32768
#define OFF_POOL 106496       // 512 x float2 = 4096
#define OFF_STAT 110592       // sL 128 | sLp 1024 | sCnt 128 | poolCnt 16
#define SMEM_TOTAL 111904

__device__ float          g_V [Bsz * Nn * 64];
__device__ __nv_bfloat16  g_Qh[Bsz * Nn * 64];
__device__ __nv_bfloat16  g_Ql[Bsz * Nn * 64];
__device__ __nv_bfloat16  g_Kh[Bsz * Nn * 64];
__device__ __nv_bfloat16  g_Kl[Bsz * Nn * 64];

// ================= helpers =================
__device__ __forceinline__ uint32_t smem_u32(const void* p) {
    uint32_t a;
    asm("{ .reg .u64 t; cvta.to.shared.u64 t, %1; cvt.u32.u64 %0, t; }" : "=r"(a) : "l"(p));
    return a;
}
__device__ __forceinline__ void cp16(uint32_t dst, const void* src) {
    asm volatile("cp.async.cg.shared.global [%0], [%1], 16;" :: "r"(dst), "l"(src));
}
#define CP_COMMIT()  asm volatile("cp.async.commit_group;" ::: "memory")
#define CP_WAIT(n)   asm volatile("cp.async.wait_group %0;" :: "n"(n) : "memory")
#define SW128(off)   ((off) ^ (((off) >> 3) & 0x70))

#define LDSM_X4(r0, r1, r2, r3, addr)                                          \
    asm volatile("ldmatrix.sync.aligned.m8n8.x4.shared.b16 {%0,%1,%2,%3}, [%4];" \
        : "=r"(r0), "=r"(r1), "=r"(r2), "=r"(r3) : "r"(addr))

__device__ __forceinline__ void mma16816(float* d, const uint32_t* a, const uint32_t* b) {
    asm volatile(
        "mma.sync.aligned.m16n8k16.row.col.f32.bf16.bf16.f32 "
        "{%0,%1,%2,%3}, {%4,%5,%6,%7}, {%8,%9}, {%0,%1,%2,%3};"
        : "+f"(d[0]), "+f"(d[1]), "+f"(d[2]), "+f"(d[3])
        : "r"(a[0]), "r"(a[1]), "r"(a[2]), "r"(a[3]), "r"(b[0]), "r"(b[1]));
}

// ---------------------------------------------------------------------------
// Kernel A: QKV projection -> bf16 hi/lo Q,K splits + fp32 V. (unchanged)
// ---------------------------------------------------------------------------
__global__ __launch_bounds__(256) void qkv_kernel(
    const float* __restrict__ x,
    const float* __restrict__ Wq, const float* __restrict__ bq,
    const float* __restrict__ Wk, const float* __restrict__ bk,
    const float* __restrict__ Wv, const float* __restrict__ bv)
{
    __shared__ float sX[64 * 68];
    int tid = threadIdx.x;
    size_t base = (size_t)blockIdx.x * 64;

#pragma unroll
    for (int i = 0; i < 4; i++) {
        int slot = i * 256 + tid;
        int row  = slot >> 4;
        int d4   = (slot & 15) << 2;
        float4 v = *(const float4*)(x + (base + row) * 64 + d4);
        *(float4*)(sX + row * 68 + d4) = v;
    }
    __syncthreads();

    int c  = tid & 63;
    int rg = tid >> 6;

#pragma unroll 1
    for (int m = 0; m < 3; m++) {
        const float* W  = (m == 0) ? Wq : (m == 1) ? Wk : Wv;
        const float* bb = (m == 0) ? bq : (m == 1) ? bk : bv;
        float wcol[64];
#pragma unroll
        for (int d = 0; d < 64; d++) wcol[d] = W[d * 64 + c];
        float bias = bb[c];

#pragma unroll 1
        for (int rr = 0; rr < 16; rr++) {
            int r = rg * 16 + rr;
            const float* xr = sX + r * 68;
            float a0 = 0.f, a1 = 0.f, a2 = 0.f, a3 = 0.f;
#pragma unroll
            for (int d = 0; d < 64; d += 4) {
                float4 xv = *(const float4*)(xr + d);
                a0 += xv.x * wcol[d];
                a1 += xv.y * wcol[d + 1];
                a2 += xv.z * wcol[d + 2];
                a3 += xv.w * wcol[d + 3];
            }
            float acc = ((a0 + a1) + (a2 + a3)) + bias;
            size_t idx = (base + r) * 64 + c;
            if (m == 2) {
                g_V[idx] = acc;
            } else {
                __nv_bfloat16 hi = __float2bfloat16(acc);
                __nv_bfloat16 lo = __float2bfloat16(acc - __bfloat162float(hi));
                if (m == 0) { g_Qh[idx] = hi; g_Ql[idx] = lo; }
                else        { g_Kh[idx] = hi; g_Kl[idx] = lo; }
            }
        }
    }
}

// ---------------------------------------------------------------------------
// Kernel B: two-pass stripless attention, BARRIER-FREE main loop.
// Warp w privately owns keys [w*256, w*256+256) and double-buffers its own
// 16-key sub-chunks via per-warp cp.async groups (wait_group + syncwarp only).
// Pass 1 = exp row-sums; pass 2 = recompute + threshold + list append.
// ---------------------------------------------------------------------------
__global__ __launch_bounds__(256, 2) void attn_kernel(float* __restrict__ out)
{
    extern __shared__ char smem[];
    float2* sList = (float2*)(smem + OFF_LIST);
    float2* sPool = (float2*)(smem + OFF_POOL);
    float*  sL    = (float*)(smem + OFF_STAT);
    float*  sLp   = (float*)(smem + OFF_STAT + 128);
    int*    sCnt  = (int*)(smem + OFF_STAT + 1152);
    int*    sPoolCnt = (int*)(smem + OFF_STAT + 1280);

    uint32_t sb = smem_u32(smem);
    int tid  = threadIdx.x;
    int wid  = tid >> 5;
    int lane = tid & 31;
    int b    = blockIdx.y;
    int i0   = blockIdx.x * Mr;

    if (tid < 32) sCnt[tid] = 0;
    if (tid == 0) *sPoolCnt = 0;

    const __nv_bfloat16* kHbase = g_Kh + ((size_t)b * Nn + wid * 256) * 64;
    const __nv_bfloat16* kLbase = g_Kl + ((size_t)b * Nn + wid * 256) * 64;
    uint32_t mykb = sb + OFF_K + wid * 8192;

    // per-lane cp.async mapping for one 16-key sub-chunk (8 x 16B per lane)
    // slot = i*32 + lane in [0,256): half = slot>>7, row = (slot>>3)&15, c16 = slot&7
    // ---- prefetch sub-chunk 0 into buf 0 ----
#pragma unroll
    for (int i = 0; i < 8; i++) {
        int slot = i * 32 + lane;
        int half = slot >> 7;
        int row  = (slot >> 3) & 15;
        int c16  = slot & 7;
        const __nv_bfloat16* src = (half ? kLbase : kHbase) + row * 64 + c16 * 8;
        cp16(mykb + half * 2048 + SW128((uint32_t)(row * 128 + c16 * 16)), src);
    }
    CP_COMMIT();

    // ---- stage Q tile [32][64] hi/lo, SW128 128B rows ----
#pragma unroll
    for (int i = 0; i < 2; i++) {
        int slot = i * 256 + tid;
        int half = slot >> 8;
        int t    = slot & 255;
        int row  = t >> 3;
        int c16  = t & 7;
        const __nv_bfloat16* src = (half ? g_Ql : g_Qh) + ((size_t)b * Nn + i0 + row) * 64 + c16 * 8;
        uint4 v = *(const uint4*)src;
        *(uint4*)(smem + OFF_Q + half * 4096 + SW128((uint32_t)(row * 128 + c16 * 16))) = v;
    }
    __syncthreads();

    // ---- resident A fragments: 2 m-tiles x 4 ksteps x 4 regs, hi + lo ----
    uint32_t aH[2][16], aL[2][16];
#pragma unroll
    for (int mt = 0; mt < 2; mt++)
#pragma unroll
        for (int ks = 0; ks < 4; ks++) {
            uint32_t off = (uint32_t)((mt * 16 + (lane & 15)) * 128 + (ks * 2 + (lane >> 4)) * 16);
            LDSM_X4(aH[mt][ks*4], aH[mt][ks*4+1], aH[mt][ks*4+2], aH[mt][ks*4+3],
                    sb + OFF_Q + SW128(off));
            LDSM_X4(aL[mt][ks*4], aL[mt][ks*4+1], aL[mt][ks*4+2], aL[mt][ks*4+3],
                    sb + OFF_Q + 4096 + SW128(off));
        }

    int r0 = lane >> 2;
    float sums[4] = {0.f, 0.f, 0.f, 0.f};        // rows r0, r0+8, r0+16, r0+24
    float thrv[4];

    // ---- barrier-free main loop: it 0-15 pass 1, 16-31 pass 2 ----
#pragma unroll 1
    for (int it = 0; it < 32; it++) {
        int t = it & 15;
        if (it < 31) {
            int tn = (it + 1) & 15;
            uint32_t kb = mykb + ((it + 1) & 1) * 4096;
#pragma unroll
            for (int i = 0; i < 8; i++) {
                int slot = i * 32 + lane;
                int half = slot >> 7;
                int row  = (slot >> 3) & 15;
                int c16  = slot & 7;
                const __nv_bfloat16* src = (half ? kLbase : kHbase) + (tn * 16 + row) * 64 + c16 * 8;
                cp16(kb + half * 2048 + SW128((uint32_t)(row * 128 + c16 * 16)), src);
            }
            CP_COMMIT();
            CP_WAIT(1);
        } else {
            CP_WAIT(0);
        }
        __syncwarp();

        uint32_t kb = mykb + (it & 1) * 4096;

#pragma unroll
        for (int nt = 0; nt < 2; nt++) {
            uint32_t rowoff = (uint32_t)((nt * 8 + (lane & 7)) * 128 + (lane >> 3) * 16);
            uint32_t bh[8], bl[8];
            LDSM_X4(bh[0], bh[1], bh[2], bh[3], kb + SW128(rowoff));
            LDSM_X4(bh[4], bh[5], bh[6], bh[7], kb + SW128(rowoff + 64));
            LDSM_X4(bl[0], bl[1], bl[2], bl[3], kb + 2048 + SW128(rowoff));
            LDSM_X4(bl[4], bl[5], bl[6], bl[7], kb + 2048 + SW128(rowoff + 64));

#pragma unroll
            for (int mt = 0; mt < 2; mt++) {
                float d0[4] = {0.f, 0.f, 0.f, 0.f};
                float d1[4] = {0.f, 0.f, 0.f, 0.f};
                mma16816(d0, &aH[mt][0],  &bh[0]);  mma16816(d1, &aH[mt][4],  &bh[2]);
                mma16816(d0, &aH[mt][8],  &bh[4]);  mma16816(d1, &aH[mt][12], &bh[6]);
                mma16816(d0, &aH[mt][0],  &bl[0]);  mma16816(d1, &aH[mt][4],  &bl[2]);
                mma16816(d0, &aH[mt][8],  &bl[4]);  mma16816(d1, &aH[mt][12], &bl[6]);
                mma16816(d0, &aL[mt][0],  &bh[0]);  mma16816(d1, &aL[mt][4],  &bh[2]);
                mma16816(d0, &aL[mt][8],  &bh[4]);  mma16816(d1, &aL[mt][12], &bh[6]);

                float e0 = __expf((d0[0] + d1[0]) - SHIFT);
                float e1 = __expf((d0[1] + d1[1]) - SHIFT);
                float e2 = __expf((d0[2] + d1[2]) - SHIFT);
                float e3 = __expf((d0[3] + d1[3]) - SHIFT);

                if (it < 16) {
                    sums[mt * 2 + 0] += e0 + e1;
                    sums[mt * 2 + 1] += e2 + e3;
                } else {
                    int ra = mt * 16 + r0, rb = ra + 8;
                    int j0 = wid * 256 + t * 16 + nt * 8 + (lane & 3) * 2;
                    float ta = thrv[mt * 2], tb = thrv[mt * 2 + 1];
                    if (e0 > ta) {
                        int p = atomicAdd(&sCnt[ra], 1);
                        if (p < CAP) sList[ra * CAP + p] = make_float2(e0, __int_as_float(j0));
                        else { int gq = atomicAdd(sPoolCnt, 1); if (gq < POOLCAP) sPool[gq] = make_float2(e0, __int_as_float((ra << 11) | j0)); }
                    }
                    if (e1 > ta) {
                        int p = atomicAdd(&sCnt[ra], 1);
                        if (p < CAP) sList[ra * CAP + p] = make_float2(e1, __int_as_float(j0 + 1));
                        else { int gq = atomicAdd(sPoolCnt, 1); if (gq < POOLCAP) sPool[gq] = make_float2(e1, __int_as_float((ra << 11) | (j0 + 1))); }
                    }
                    if (e2 > tb) {
                        int p = atomicAdd(&sCnt[rb], 1);
                        if (p < CAP) sList[rb * CAP + p] = make_float2(e2, __int_as_float(j0));
                        else { int gq = atomicAdd(sPoolCnt, 1); if (gq < POOLCAP) sPool[gq] = make_float2(e2, __int_as_float((rb << 11) | j0)); }
                    }
                    if (e3 > tb) {
                        int p = atomicAdd(&sCnt[rb], 1);
                        if (p < CAP) sList[rb * CAP + p] = make_float2(e3, __int_as_float(j0 + 1));
                        else { int gq = atomicAdd(sPoolCnt, 1); if (gq < POOLCAP) sPool[gq] = make_float2(e3, __int_as_float((rb << 11) | (j0 + 1))); }
                    }
                }
            }
        }

        if (it == 15) {
            // pass boundary: reduce row sums -> L, derive thresholds
#pragma unroll
            for (int s = 0; s < 4; s++) {
                sums[s] += __shfl_xor_sync(0xffffffffu, sums[s], 1);
                sums[s] += __shfl_xor_sync(0xffffffffu, sums[s], 2);
            }
            if ((lane & 3) == 0) {
                sLp[(r0     ) * 8 + wid] = sums[0];
                sLp[(r0 +  8) * 8 + wid] = sums[1];
                sLp[(r0 + 16) * 8 + wid] = sums[2];
                sLp[(r0 + 24) * 8 + wid] = sums[3];
            }
            __syncthreads();
            if (tid < 32) {
                float s = 0.f;
#pragma unroll
                for (int wd = 0; wd < 8; wd++) s += sLp[tid * 8 + wd];
                sL[tid] = s;
            }
            __syncthreads();
            thrv[0] = sL[r0]      * (1.0f / 2048.0f);
            thrv[1] = sL[r0 + 8]  * (1.0f / 2048.0f);
            thrv[2] = sL[r0 + 16] * (1.0f / 2048.0f);
            thrv[3] = sL[r0 + 24] * (1.0f / 2048.0f);
        }
    }
    __syncthreads();   // all appends visible

    // ---- P.V: sparse gather from lists; warp handles 4 rows ----
    const float* vb = g_V + (size_t)b * Nn * 64;
    int tx = lane * 2;
#pragma unroll 1
    for (int rr = 0; rr < 4; rr++) {
        int r = wid * 4 + rr;
        int cnt = sCnt[r];
        int cl  = cnt < CAP ? cnt : CAP;
        float Lr = sL[r];
        const float2* lst = sList + r * CAP;
        float2 acc = make_float2(0.f, 0.f);

        int i = 0;
        for (; i + 4 <= cl; i += 4) {
            float2 p0 = lst[i], p1 = lst[i + 1], p2 = lst[i + 2], p3 = lst[i + 3];
            int j0 = __float_as_int(p0.y), j1 = __float_as_int(p1.y);
            int j2 = __float_as_int(p2.y), j3 = __float_as_int(p3.y);
            float2 v0 = *(const float2*)(vb + (size_t)j0 * 64 + tx);
            float2 v1 = *(const float2*)(vb + (size_t)j1 * 64 + tx);
            float2 v2 = *(const float2*)(vb + (size_t)j2 * 64 + tx);
            float2 v3 = *(const float2*)(vb + (size_t)j3 * 64 + tx);
            acc.x += p0.x * v0.x; acc.y += p0.x * v0.y;
            acc.x += p1.x * v1.x; acc.y += p1.x * v1.y;
            acc.x += p2.x * v2.x; acc.y += p2.x * v2.y;
            acc.x += p3.x * v3.x; acc.y += p3.x * v3.y;
        }
        for (; i < cl; i++) {
            float2 p = lst[i];
            int j = __float_as_int(p.y);
            float2 v = *(const float2*)(vb + (size_t)j * 64 + tx);
            acc.x += p.x * v.x; acc.y += p.x * v.y;
        }
        if (cnt > CAP) {
            int pc = *sPoolCnt;
            if (pc > POOLCAP) pc = POOLCAP;
            for (int k = 0; k < pc; k++) {
                float2 p = sPool[k];
                int idx = __float_as_int(p.y);
                if ((idx >> 11) == r) {
                    int j = idx & 2047;
                    float2 v = *(const float2*)(vb + (size_t)j * 64 + tx);
                    acc.x += p.x * v.x; acc.y += p.x * v.y;
                }
            }
        }

        float invL = 1.0f / Lr;
        *(float2*)(out + ((size_t)b * Nn + i0 + r) * 64 + tx) =
            make_float2(acc.x * invL, acc.y * invL);
    }
}

// ---------------------------------------------------------------------------
extern "C" void kernel_launch(void* const* d_in, const int* in_sizes, int n_in,
                              void* d_out, int out_size)
{
    const float* x  = (const float*)d_in[0];
    const float* Wq = (const float*)d_in[1];
    const float* bq = (const float*)d_in[2];
    const float* Wk = (const float*)d_in[3];
    const float* bk = (const float*)d_in[4];
    const float* Wv = (const float*)d_in[5];
    const float* bv = (const float*)d_in[6];
    float* out = (float*)d_out;

    cudaFuncSetAttribute(attn_kernel,
                         cudaFuncAttributeMaxDynamicSharedMemorySize, SMEM_TOTAL);

    qkv_kernel<<<(Bsz * Nn) / 64, 256>>>(x, Wq, bq, Wk, bk, Wv, bv);
    attn_kernel<<<dim3(Nn / Mr, Bsz), 256, SMEM_TOTAL>>>(out);
}